// round 16
// baseline (speedup 1.0000x reference)
#include <cuda_runtime.h>
#include <cuda_fp16.h>
#include <math.h>
#include <stdint.h>

#define N_NODES    524288
#define NUM_GRAPHS 8192
#define HDIM       256
#define NCHUNK     4
#define CHUNK_N    (N_NODES / NCHUNK)      // 131072
#define CHUNK_SHIFT 17                      // log2(CHUNK_N)

// ---------------- scratch (static device globals; no allocation) ----------------
__device__ float  g_s[N_NODES];
__device__ int    g_start[NUM_GRAPHS + 1];
__device__ float  g_pooled[NUM_GRAPHS * 768];
__device__ __half g_Wf_h[512 * 768];             // fused weights, fp16, N-major
__device__ float  g_bf[512];
__device__ __half g_hid_h[NUM_GRAPHS * 512];     // gelu hidden, fp16
__device__ __half g_Wc2t_h[256 * 512];           // Wc2 transposed fp16 N-major
__device__ float  g_W1t[128 * 256];              // W_att1 transposed (N-major)

// ---------------- helpers ----------------
__device__ __forceinline__ uint32_t f2h2(float a, float b) {
    uint32_t u;
    asm("cvt.rn.f16x2.f32 %0, %2, %1;" : "=r"(u) : "f"(a), "f"(b));
    return u;
}

__device__ __forceinline__ void mma_f16(float c[4],
    uint32_t a0, uint32_t a1, uint32_t a2, uint32_t a3,
    uint32_t b0, uint32_t b1)
{
    asm volatile(
        "mma.sync.aligned.m16n8k16.row.col.f32.f16.f16.f32 "
        "{%0,%1,%2,%3}, {%4,%5,%6,%7}, {%8,%9}, {%0,%1,%2,%3};"
        : "+f"(c[0]), "+f"(c[1]), "+f"(c[2]), "+f"(c[3])
        : "r"(a0), "r"(a1), "r"(a2), "r"(a3), "r"(b0), "r"(b1));
}

// ============================================================================
// fused prep: [0,2048) seg_start | [2048,2080) transpose W1 |
//             [2080,2176) Wf fp16 N-major | [2176,2208) bf |
//             [2208,2336) transpose+cvt Wc2 -> fp16 N-major
// ============================================================================
#define PREP_BLOCKS (2048 + 32 + 96 + 32 + 128)

__global__ __launch_bounds__(256)
void prep_kernel(const int* __restrict__ batch, const float* __restrict__ W1,
                 const float* __restrict__ Wm, const float* __restrict__ Wx,
                 const float* __restrict__ Ww, const float* __restrict__ Wc1,
                 const float* __restrict__ bm, const float* __restrict__ bx,
                 const float* __restrict__ bw, const float* __restrict__ bc1,
                 const float* __restrict__ Wc2, float* __restrict__ W1t)
{
    __shared__ float sbuf[2176];
    const int b = blockIdx.x, tid = threadIdx.x;

    if (b < 2048) {
        int n = b * 256 + tid;
        int v  = batch[n];
        int pv = (n == 0) ? -1 : batch[n - 1];
        if (v >= NUM_GRAPHS) v = NUM_GRAPHS - 1;
        if (pv < -1) pv = -1;
        if (pv > v)  pv = v;
        for (int g = pv + 1; g <= v; g++) g_start[g] = n;
        if (n == N_NODES - 1)
            for (int g = v + 1; g <= NUM_GRAPHS; g++) g_start[g] = N_NODES;
    } else if (b < 2080) {
        float (*t)[33] = (float(*)[33])sbuf;
        int tb = b - 2048;
        int bx0 = (tb & 7) * 32;
        int by0 = (tb >> 3) * 32;
        int tx = tid & 31, ty = tid >> 5;
        #pragma unroll
        for (int i = 0; i < 32; i += 8)
            t[ty + i][tx] = W1[(size_t)(bx0 + ty + i) * 128 + by0 + tx];
        __syncthreads();
        #pragma unroll
        for (int i = 0; i < 32; i += 8)
            W1t[(size_t)(by0 + ty + i) * 256 + bx0 + tx] = t[tx][ty + i];
    } else if (b < 2176) {
        float (*As)[68] = (float(*)[68])sbuf;
        float (*Bs)[68] = (float(*)[68])(sbuf + 16 * 68);
        int wb = b - 2080;
        int bx0 = wb & 3, by0 = (wb >> 2) & 7, z = wb >> 5;
        const float* A = (z == 0) ? Wm : (z == 1) ? Wx : Ww;
        const float* B = Wc1 + (size_t)z * 256 * 512;

        int tx = tid & 15, ty = tid >> 4;
        int ar = tid >> 2, ac = (tid & 3) << 2;
        int br = tid >> 4, bc = (tid & 15) << 2;

        float acc[4][4];
        #pragma unroll
        for (int i = 0; i < 4; i++)
            #pragma unroll
            for (int j = 0; j < 4; j++) acc[i][j] = 0.f;

        for (int k0 = 0; k0 < 256; k0 += 16) {
            float4 va = *(const float4*)(A + (size_t)(bx0 * 64 + ar) * 256 + k0 + ac);
            As[ac + 0][ar] = va.x; As[ac + 1][ar] = va.y;
            As[ac + 2][ar] = va.z; As[ac + 3][ar] = va.w;
            float4 vb = *(const float4*)(B + (size_t)(k0 + br) * 512 + by0 * 64 + bc);
            *(float4*)&Bs[br][bc] = vb;
            __syncthreads();
            #pragma unroll
            for (int kk = 0; kk < 16; kk++) {
                float a[4], bb[4];
                #pragma unroll
                for (int i = 0; i < 4; i++) a[i] = As[kk][ty * 4 + i];
                #pragma unroll
                for (int j = 0; j < 4; j++) bb[j] = Bs[kk][tx * 4 + j];
                #pragma unroll
                for (int i = 0; i < 4; i++)
                    #pragma unroll
                    for (int j = 0; j < 4; j++)
                        acc[i][j] = fmaf(a[i], bb[j], acc[i][j]);
            }
            __syncthreads();
        }
        #pragma unroll
        for (int i = 0; i < 4; i++) {
            int row = z * 256 + bx0 * 64 + ty * 4 + i;
            #pragma unroll
            for (int j = 0; j < 4; j++) {
                int col = by0 * 64 + tx * 4 + j;
                g_Wf_h[(size_t)col * 768 + row] = __float2half(acc[i][j]);
            }
        }
    } else if (b < 2208) {
        int fb = b - 2176;
        int cl = tid & 15, p = tid >> 4;
        int c = fb * 16 + cl;
        float acc = 0.f;
        for (int j = p * 16; j < p * 16 + 16; j++) {
            acc = fmaf(bm[j], Wc1[(size_t)j * 512 + c], acc);
            acc = fmaf(bx[j], Wc1[(size_t)(256 + j) * 512 + c], acc);
            acc = fmaf(bw[j], Wc1[(size_t)(512 + j) * 512 + c], acc);
        }
        sbuf[p * 16 + cl] = acc;
        __syncthreads();
        if (p == 0) {
            float s = bc1[c];
            #pragma unroll
            for (int q = 0; q < 16; q++) s += sbuf[q * 16 + cl];
            g_bf[c] = s;
        }
    } else {
        float (*t)[33] = (float(*)[33])sbuf;
        int tb = b - 2208;
        int kb = (tb & 15) * 32;
        int nb = (tb >> 4) * 32;
        int tx = tid & 31, ty = tid >> 5;
        #pragma unroll
        for (int i = 0; i < 32; i += 8)
            t[ty + i][tx] = Wc2[(size_t)(kb + ty + i) * 256 + nb + tx];
        __syncthreads();
        #pragma unroll
        for (int i = 0; i < 32; i += 8)
            g_Wc2t_h[(size_t)(nb + ty + i) * 512 + kb + tx] = __float2half(t[tx][ty + i]);
    }
}

// ============================================================================
// score v4: s = tanh(x@W1 + b1) @ W2 + b2 via fp16 mma (fp32 accum).
// Called per node-chunk (x, s_out pre-offset by the launcher).
// ============================================================================
#define V4_AW (2 * 256 * 20)
#define V4_BW (2 * 128 * 20)
#define V4_SMEM ((V4_AW + V4_BW + 256 * 4) * 4)

__global__ __launch_bounds__(512, 1)
void score_mma_v4(const float* __restrict__ x, const float* __restrict__ W1t,
                  const float* __restrict__ b1, const float* __restrict__ W2,
                  const float* __restrict__ b2v, float* __restrict__ s_out)
{
    extern __shared__ uint32_t sm[];
    uint32_t* As2 = sm;
    uint32_t* Bs2 = sm + V4_AW;
    float*   psum = (float*)(sm + V4_AW + V4_BW);

    const int tid  = threadIdx.x;
    const int lane = tid & 31, warp = tid >> 5;
    const int wy = warp >> 2, wx = warp & 3;
    const int g = lane >> 2, t = lane & 3;

    const float* Ab = x + (size_t)blockIdx.x * 256 * 256;

    float c[4][4][4];
    #pragma unroll
    for (int mf = 0; mf < 4; mf++)
        #pragma unroll
        for (int nf = 0; nf < 4; nf++)
            #pragma unroll
            for (int r = 0; r < 4; r++) c[mf][nf][r] = 0.f;

    float4 areg[4], breg[2];

    auto ldg = [&](int ch) {
        #pragma unroll
        for (int i = 0; i < 4; i++) {
            int fid = tid + i * 512;
            int row = fid >> 3, c4 = (fid & 7) << 2;
            areg[i] = *(const float4*)(Ab + (size_t)row * 256 + ch * 32 + c4);
        }
        #pragma unroll
        for (int i = 0; i < 2; i++) {
            int fid = tid + i * 512;
            int row = fid >> 3, c4 = (fid & 7) << 2;
            breg[i] = *(const float4*)(W1t + (size_t)row * 256 + ch * 32 + c4);
        }
    };
    auto sts = [&](int ch) {
        const int buf = ch & 1;
        #pragma unroll
        for (int i = 0; i < 4; i++) {
            int fid = tid + i * 512;
            int row = fid >> 3, h2c = (fid & 7) << 1;
            uint2 v = { f2h2(areg[i].x, areg[i].y), f2h2(areg[i].z, areg[i].w) };
            *(uint2*)&As2[(buf * 256 + row) * 20 + h2c] = v;
        }
        #pragma unroll
        for (int i = 0; i < 2; i++) {
            int fid = tid + i * 512;
            int row = fid >> 3, h2c = (fid & 7) << 1;
            uint2 v = { f2h2(breg[i].x, breg[i].y), f2h2(breg[i].z, breg[i].w) };
            *(uint2*)&Bs2[(buf * 128 + row) * 20 + h2c] = v;
        }
    };

    ldg(0); sts(0); ldg(1);

    #pragma unroll
    for (int ch = 0; ch < 8; ch++) {
        __syncthreads();
        if (ch + 1 < 8) sts(ch + 1);
        if (ch + 2 < 8) ldg(ch + 2);

        const uint32_t* A_s = As2 + (ch & 1) * 256 * 20;
        const uint32_t* B_s = Bs2 + (ch & 1) * 128 * 20;

        #pragma unroll
        for (int kk = 0; kk < 2; kk++) {
            const int k2 = kk * 8;
            uint32_t a[4][4], b[4][2];
            #pragma unroll
            for (int mf = 0; mf < 4; mf++) {
                int row = wy * 64 + mf * 16 + g;
                a[mf][0] = A_s[row * 20 + k2 + t];
                a[mf][1] = A_s[(row + 8) * 20 + k2 + t];
                a[mf][2] = A_s[row * 20 + k2 + t + 4];
                a[mf][3] = A_s[(row + 8) * 20 + k2 + t + 4];
            }
            #pragma unroll
            for (int nf = 0; nf < 4; nf++) {
                int col = wx * 32 + nf * 8 + g;
                b[nf][0] = B_s[col * 20 + k2 + t];
                b[nf][1] = B_s[col * 20 + k2 + t + 4];
            }
            #pragma unroll
            for (int mf = 0; mf < 4; mf++)
                #pragma unroll
                for (int nf = 0; nf < 4; nf++)
                    mma_f16(c[mf][nf], a[mf][0], a[mf][1], a[mf][2], a[mf][3],
                            b[nf][0], b[nf][1]);
        }
    }

    #pragma unroll
    for (int mf = 0; mf < 4; mf++) {
        #pragma unroll
        for (int h = 0; h < 2; h++) {
            float p = 0.f;
            #pragma unroll
            for (int nf = 0; nf < 4; nf++) {
                #pragma unroll
                for (int e = 0; e < 2; e++) {
                    int col = wx * 32 + nf * 8 + 2 * t + e;
                    float v = c[mf][nf][h * 2 + e] + __ldg(&b1[col]);
                    p += tanhf(v) * __ldg(&W2[col]);
                }
            }
            p += __shfl_xor_sync(0xffffffffu, p, 1);
            p += __shfl_xor_sync(0xffffffffu, p, 2);
            if (t == 0) psum[(wy * 64 + mf * 16 + g + 8 * h) * 4 + wx] = p;
        }
    }
    __syncthreads();
    if (tid < 256) {
        float s = psum[tid * 4] + psum[tid * 4 + 1] + psum[tid * 4 + 2] + psum[tid * 4 + 3];
        s_out[(size_t)blockIdx.x * 256 + tid] = s + b2v[0];
    }
}

// ---------------- per-graph softmax + pools, chunked by last-node ------------
__global__ __launch_bounds__(256)
void pool_kernel(const float* __restrict__ x, const float* __restrict__ s,
                 float* __restrict__ pooled, int chunk)
{
    __shared__ float red[256];
    __shared__ float w_sm[256];
    __shared__ float4 rbuf[256];
    int g = blockIdx.x;
    int beg = g_start[g], end = g_start[g + 1];
    if (beg < 0) beg = 0;
    if (end > N_NODES) end = N_NODES;

    // process this graph only in the chunk containing its last node
    int key = (end > 0) ? (end - 1) : 0;
    if ((key >> CHUNK_SHIFT) != chunk) return;

    int cnt = end - beg;
    int tid = threadIdx.x;

    float m = -3.402823466e38f;
    for (int i = beg + tid; i < end; i += 256) m = fmaxf(m, s[i]);
    red[tid] = m; __syncthreads();
    for (int off = 128; off > 0; off >>= 1) {
        if (tid < off) red[tid] = fmaxf(red[tid], red[tid + off]);
        __syncthreads();
    }
    float smax = red[0];
    __syncthreads();

    float e = 0.f;
    for (int i = beg + tid; i < end; i += 256) e += expf(s[i] - smax);
    red[tid] = e; __syncthreads();
    for (int off = 128; off > 0; off >>= 1) {
        if (tid < off) red[tid] += red[tid + off];
        __syncthreads();
    }
    float inv_den = (cnt > 0) ? (1.f / red[0]) : 0.f;
    __syncthreads();

    const int nl = tid >> 6;
    const int c4 = (tid & 63) << 2;
    float4 aw = {0.f, 0.f, 0.f, 0.f}, as4 = {0.f, 0.f, 0.f, 0.f};
    float4 am = {-3.402823466e38f, -3.402823466e38f, -3.402823466e38f, -3.402823466e38f};

    for (int c0 = beg; c0 < end; c0 += 256) {
        int clen = min(256, end - c0);
        if (tid < clen) w_sm[tid] = expf(s[c0 + tid] - smax) * inv_den;
        __syncthreads();
        const float* xb = x + (size_t)c0 * 256 + c4;
        int j = nl;
        for (; j + 12 < clen; j += 16) {
            float w0 = w_sm[j],     w1 = w_sm[j + 4];
            float w2 = w_sm[j + 8], w3 = w_sm[j + 12];
            float4 x0 = *(const float4*)(xb + (size_t)j * 256);
            float4 x1 = *(const float4*)(xb + (size_t)(j + 4) * 256);
            float4 x2 = *(const float4*)(xb + (size_t)(j + 8) * 256);
            float4 x3 = *(const float4*)(xb + (size_t)(j + 12) * 256);
            aw.x = fmaf(w0, x0.x, aw.x); aw.y = fmaf(w0, x0.y, aw.y);
            aw.z = fmaf(w0, x0.z, aw.z); aw.w = fmaf(w0, x0.w, aw.w);
            as4.x += x0.x; as4.y += x0.y; as4.z += x0.z; as4.w += x0.w;
            am.x = fmaxf(am.x, x0.x); am.y = fmaxf(am.y, x0.y);
            am.z = fmaxf(am.z, x0.z); am.w = fmaxf(am.w, x0.w);
            aw.x = fmaf(w1, x1.x, aw.x); aw.y = fmaf(w1, x1.y, aw.y);
            aw.z = fmaf(w1, x1.z, aw.z); aw.w = fmaf(w1, x1.w, aw.w);
            as4.x += x1.x; as4.y += x1.y; as4.z += x1.z; as4.w += x1.w;
            am.x = fmaxf(am.x, x1.x); am.y = fmaxf(am.y, x1.y);
            am.z = fmaxf(am.z, x1.z); am.w = fmaxf(am.w, x1.w);
            aw.x = fmaf(w2, x2.x, aw.x); aw.y = fmaf(w2, x2.y, aw.y);
            aw.z = fmaf(w2, x2.z, aw.z); aw.w = fmaf(w2, x2.w, aw.w);
            as4.x += x2.x; as4.y += x2.y; as4.z += x2.z; as4.w += x2.w;
            am.x = fmaxf(am.x, x2.x); am.y = fmaxf(am.y, x2.y);
            am.z = fmaxf(am.z, x2.z); am.w = fmaxf(am.w, x2.w);
            aw.x = fmaf(w3, x3.x, aw.x); aw.y = fmaf(w3, x3.y, aw.y);
            aw.z = fmaf(w3, x3.z, aw.z); aw.w = fmaf(w3, x3.w, aw.w);
            as4.x += x3.x; as4.y += x3.y; as4.z += x3.z; as4.w += x3.w;
            am.x = fmaxf(am.x, x3.x); am.y = fmaxf(am.y, x3.y);
            am.z = fmaxf(am.z, x3.w > -1e38f ? x3.z : x3.z); am.w = fmaxf(am.w, x3.w);
        }
        for (; j < clen; j += 4) {
            float w = w_sm[j];
            float4 xv = *(const float4*)(xb + (size_t)j * 256);
            aw.x = fmaf(w, xv.x, aw.x); aw.y = fmaf(w, xv.y, aw.y);
            aw.z = fmaf(w, xv.z, aw.z); aw.w = fmaf(w, xv.w, aw.w);
            as4.x += xv.x; as4.y += xv.y; as4.z += xv.z; as4.w += xv.w;
            am.x = fmaxf(am.x, xv.x); am.y = fmaxf(am.y, xv.y);
            am.z = fmaxf(am.z, xv.z); am.w = fmaxf(am.w, xv.w);
        }
        __syncthreads();
    }

    size_t base = (size_t)g * 768;
    float inv_c = (cnt > 0) ? (1.f / (float)cnt) : 0.f;

    rbuf[tid] = as4; __syncthreads();
    if (tid < 64) {
        float4 a = rbuf[tid], b = rbuf[tid + 64], c = rbuf[tid + 128], d = rbuf[tid + 192];
        float4 r = { (a.x + b.x + c.x + d.x) * inv_c, (a.y + b.y + c.y + d.y) * inv_c,
                     (a.z + b.z + c.z + d.z) * inv_c, (a.w + b.w + c.w + d.w) * inv_c };
        *(float4*)(pooled + base + tid * 4) = r;
    }
    __syncthreads();
    rbuf[tid] = am; __syncthreads();
    if (tid < 64) {
        float4 a = rbuf[tid], b = rbuf[tid + 64], c = rbuf[tid + 128], d = rbuf[tid + 192];
        float4 r = { fmaxf(fmaxf(a.x, b.x), fmaxf(c.x, d.x)),
                     fmaxf(fmaxf(a.y, b.y), fmaxf(c.y, d.y)),
                     fmaxf(fmaxf(a.z, b.z), fmaxf(c.z, d.z)),
                     fmaxf(fmaxf(a.w, b.w), fmaxf(c.w, d.w)) };
        if (cnt <= 0) r = make_float4(0.f, 0.f, 0.f, 0.f);
        *(float4*)(pooled + base + 256 + tid * 4) = r;
    }
    __syncthreads();
    rbuf[tid] = aw; __syncthreads();
    if (tid < 64) {
        float4 a = rbuf[tid], b = rbuf[tid + 64], c = rbuf[tid + 128], d = rbuf[tid + 192];
        float4 r = { a.x + b.x + c.x + d.x, a.y + b.y + c.y + d.y,
                     a.z + b.z + c.z + d.z, a.w + b.w + c.w + d.w };
        if (cnt <= 0) r = make_float4(0.f, 0.f, 0.f, 0.f);
        *(float4*)(pooled + base + 512 + tid * 4) = r;
    }
}

// ============================================================================
// gemm1 fp16 (wide warp tiles): hid = gelu(pooled @ Wf + bf) -> fp16
// ============================================================================
#define G1_AW (2 * 128 * 20)
#define G1_BW (2 * 256 * 20)
#define G1_SMEM ((G1_AW + G1_BW) * 4)

__global__ __launch_bounds__(256)
void gemm1_f16(const float* __restrict__ A, const __half* __restrict__ Bh,
               const float* __restrict__ bias, __half* __restrict__ C)
{
    extern __shared__ uint32_t sm[];
    uint32_t* As2 = sm;
    uint32_t* Bs2 = sm + G1_AW;

    const int tid  = threadIdx.x;
    const int lane = tid & 31, warp = tid >> 5;
    const int wy = warp >> 2, wx = warp & 3;
    const int g = lane >> 2, t = lane & 3;

    const float*  Ab = A  + (size_t)blockIdx.x * 128 * 768;
    const __half* Bb = Bh + (size_t)blockIdx.y * 256 * 768;

    float c[4][8][4];
    #pragma unroll
    for (int mf = 0; mf < 4; mf++)
        #pragma unroll
        for (int nf = 0; nf < 8; nf++)
            #pragma unroll
            for (int r = 0; r < 4; r++) c[mf][nf][r] = 0.f;

    float4 areg[4];
    uint4  breg[4];

    auto ldg = [&](int ch) {
        #pragma unroll
        for (int i = 0; i < 4; i++) {
            int fid = tid + i * 256;
            int row = fid >> 3, c4 = (fid & 7) << 2;
            areg[i] = *(const float4*)(Ab + (size_t)row * 768 + ch * 32 + c4);
        }
        #pragma unroll
        for (int i = 0; i < 4; i++) {
            int fid = tid + i * 256;
            int col = fid >> 2, q = fid & 3;
            breg[i] = *(const uint4*)(Bb + (size_t)col * 768 + ch * 32 + q * 8);
        }
    };
    auto sts = [&](int ch) {
        const int buf = ch & 1;
        #pragma unroll
        for (int i = 0; i < 4; i++) {
            int fid = tid + i * 256;
            int row = fid >> 3, h2c = (fid & 7) << 1;
            uint2 v = { f2h2(areg[i].x, areg[i].y), f2h2(areg[i].z, areg[i].w) };
            *(uint2*)&As2[(buf * 128 + row) * 20 + h2c] = v;
        }
        #pragma unroll
        for (int i = 0; i < 4; i++) {
            int fid = tid + i * 256;
            int col = fid >> 2, q = fid & 3;
            *(uint4*)&Bs2[(buf * 256 + col) * 20 + q * 4] = breg[i];
        }
    };

    ldg(0); sts(0); ldg(1);

    for (int ch = 0; ch < 24; ch++) {
        __syncthreads();
        if (ch + 1 < 24) sts(ch + 1);
        if (ch + 2 < 24) ldg(ch + 2);

        const uint32_t* A_s = As2 + (ch & 1) * 128 * 20;
        const uint32_t* B_s = Bs2 + (ch & 1) * 256 * 20;

        #pragma unroll
        for (int kk = 0; kk < 2; kk++) {
            const int k2 = kk * 8;
            uint32_t a[4][4], b[8][2];
            #pragma unroll
            for (int mf = 0; mf < 4; mf++) {
                int row = wy * 64 + mf * 16 + g;
                a[mf][0] = A_s[row * 20 + k2 + t];
                a[mf][1] = A_s[(row + 8) * 20 + k2 + t];
                a[mf][2] = A_s[row * 20 + k2 + t + 4];
                a[mf][3] = A_s[(row + 8) * 20 + k2 + t + 4];
            }
            #pragma unroll
            for (int nf = 0; nf < 8; nf++) {
                int col = wx * 64 + nf * 8 + g;
                b[nf][0] = B_s[col * 20 + k2 + t];
                b[nf][1] = B_s[col * 20 + k2 + t + 4];
            }
            #pragma unroll
            for (int mf = 0; mf < 4; mf++)
                #pragma unroll
                for (int nf = 0; nf < 8; nf++)
                    mma_f16(c[mf][nf], a[mf][0], a[mf][1], a[mf][2], a[mf][3],
                            b[nf][0], b[nf][1]);
        }
    }

    #pragma unroll
    for (int mf = 0; mf < 4; mf++) {
        #pragma unroll
        for (int h = 0; h < 2; h++) {
            int row = blockIdx.x * 128 + wy * 64 + mf * 16 + g + 8 * h;
            #pragma unroll
            for (int nf = 0; nf < 8; nf++) {
                int col = blockIdx.y * 256 + wx * 64 + nf * 8 + 2 * t;
                float v0 = c[mf][nf][h * 2 + 0] + __ldg(&bias[col]);
                float v1 = c[mf][nf][h * 2 + 1] + __ldg(&bias[col + 1]);
                v0 = 0.5f * v0 * (1.f + erff(v0 * 0.70710678118654752f));
                v1 = 0.5f * v1 * (1.f + erff(v1 * 0.70710678118654752f));
                *(uint32_t*)&C[(size_t)row * 512 + col] = f2h2(v0, v1);
            }
        }
    }
}

// ============================================================================
// gemm2+LN fused: out = LN(hid_h[8192,512] @ Wc2t_h + bc2) * gamma + beta
// ============================================================================
#define G2_AW (2 * 128 * 20)
#define G2_BW (2 * 256 * 20)
#define G2_SMEM ((G2_AW + G2_BW + 128 * 4 * 2) * 4)

__global__ __launch_bounds__(256)
void gemm2_f16_ln(const __half* __restrict__ A, const __half* __restrict__ Bh,
                  const float* __restrict__ bias, const float* __restrict__ gamma,
                  const float* __restrict__ beta, float* __restrict__ out)
{
    extern __shared__ uint32_t sm[];
    uint32_t* As2  = sm;
    uint32_t* Bs2  = sm + G2_AW;
    float*   psumS = (float*)(sm + G2_AW + G2_BW);
    float*   psumQ = psumS + 128 * 4;

    const int tid  = threadIdx.x;
    const int lane = tid & 31, warp = tid >> 5;
    const int wy = warp >> 2, wx = warp & 3;
    const int g = lane >> 2, t = lane & 3;

    const __half* Ab = A + (size_t)blockIdx.x * 128 * 512;

    float c[4][8][4];
    #pragma unroll
    for (int mf = 0; mf < 4; mf++)
        #pragma unroll
        for (int nf = 0; nf < 8; nf++)
            #pragma unroll
            for (int r = 0; r < 4; r++) c[mf][nf][r] = 0.f;

    uint4 areg[2], breg[4];

    auto ldg = [&](int ch) {
        #pragma unroll
        for (int i = 0; i < 2; i++) {
            int fid = tid + i * 256;
            int row = fid >> 2, q = fid & 3;
            areg[i] = *(const uint4*)(Ab + (size_t)row * 512 + ch * 32 + q * 8);
        }
        #pragma unroll
        for (int i = 0; i < 4; i++) {
            int fid = tid + i * 256;
            int col = fid >> 2, q = fid & 3;
            breg[i] = *(const uint4*)(Bh + (size_t)col * 512 + ch * 32 + q * 8);
        }
    };
    auto sts = [&](int ch) {
        const int buf = ch & 1;
        #pragma unroll
        for (int i = 0; i < 2; i++) {
            int fid = tid + i * 256;
            int row = fid >> 2, q = fid & 3;
            *(uint4*)&As2[(buf * 128 + row) * 20 + q * 4] = areg[i];
        }
        #pragma unroll
        for (int i = 0; i < 4; i++) {
            int fid = tid + i * 256;
            int col = fid >> 2, q = fid & 3;
            *(uint4*)&Bs2[(buf * 256 + col) * 20 + q * 4] = breg[i];
        }
    };

    ldg(0); sts(0); ldg(1);

    for (int ch = 0; ch < 16; ch++) {
        __syncthreads();
        if (ch + 1 < 16) sts(ch + 1);
        if (ch + 2 < 16) ldg(ch + 2);

        const uint32_t* A_s = As2 + (ch & 1) * 128 * 20;
        const uint32_t* B_s = Bs2 + (ch & 1) * 256 * 20;

        #pragma unroll
        for (int kk = 0; kk < 2; kk++) {
            const int k2 = kk * 8;
            uint32_t a[4][4], b[8][2];
            #pragma unroll
            for (int mf = 0; mf < 4; mf++) {
                int row = wy * 64 + mf * 16 + g;
                a[mf][0] = A_s[row * 20 + k2 + t];
                a[mf][1] = A_s[(row + 8) * 20 + k2 + t];
                a[mf][2] = A_s[row * 20 + k2 + t + 4];
                a[mf][3] = A_s[(row + 8) * 20 + k2 + t + 4];
            }
            #pragma unroll
            for (int nf = 0; nf < 8; nf++) {
                int col = wx * 64 + nf * 8 + g;
                b[nf][0] = B_s[col * 20 + k2 + t];
                b[nf][1] = B_s[col * 20 + k2 + t + 4];
            }
            #pragma unroll
            for (int mf = 0; mf < 4; mf++)
                #pragma unroll
                for (int nf = 0; nf < 8; nf++)
                    mma_f16(c[mf][nf], a[mf][0], a[mf][1], a[mf][2], a[mf][3],
                            b[nf][0], b[nf][1]);
        }
    }
    __syncthreads();

    #pragma unroll
    for (int mf = 0; mf < 4; mf++) {
        #pragma unroll
        for (int h = 0; h < 2; h++) {
            float ps = 0.f, pq = 0.f;
            #pragma unroll
            for (int nf = 0; nf < 8; nf++) {
                #pragma unroll
                for (int e = 0; e < 2; e++) {
                    int col = wx * 64 + nf * 8 + 2 * t + e;
                    float v = c[mf][nf][h * 2 + e] + __ldg(&bias[col]);
                    c[mf][nf][h * 2 + e] = v;
                    ps += v; pq += v * v;
                }
            }
            ps += __shfl_xor_sync(0xffffffffu, ps, 1);
            ps += __shfl_xor_sync(0xffffffffu, ps, 2);
            pq += __shfl_xor_sync(0xffffffffu, pq, 1);
            pq += __shfl_xor_sync(0xffffffffu, pq, 2);
            if (t == 0) {
                int r = wy * 64 + mf * 16 + g + 8 * h;
                psumS[r * 4 + wx] = ps;
                psumQ[r * 4 + wx] = pq;
            }
        }
    }
    __syncthreads();

    #pragma unroll
    for (int mf = 0; mf < 4; mf++) {
        #pragma unroll
        for (int h = 0; h < 2; h++) {
            int r = wy * 64 + mf * 16 + g + 8 * h;
            float sum = psumS[r * 4] + psumS[r * 4 + 1] + psumS[r * 4 + 2] + psumS[r * 4 + 3];
            float sq  = psumQ[r * 4] + psumQ[r * 4 + 1] + psumQ[r * 4 + 2] + psumQ[r * 4 + 3];
            float mu  = sum * (1.f / 256.f);
            float var = sq * (1.f / 256.f) - mu * mu;
            float rs  = rsqrtf(var + 1e-5f);
            int grow = blockIdx.x * 128 + r;
            #pragma unroll
            for (int nf = 0; nf < 8; nf++) {
                int col = wx * 64 + nf * 8 + 2 * t;
                float v0 = (c[mf][nf][h * 2 + 0] - mu) * rs * __ldg(&gamma[col])     + __ldg(&beta[col]);
                float v1 = (c[mf][nf][h * 2 + 1] - mu) * rs * __ldg(&gamma[col + 1]) + __ldg(&beta[col + 1]);
                float2 st = { v0, v1 };
                *(float2*)(out + (size_t)grow * 256 + col) = st;
            }
        }
    }
}

// ---------------- launcher: score/pool software pipeline across 2 streams -----
static cudaStream_t g_s2 = nullptr;
static cudaEvent_t  g_ev[NCHUNK];
static cudaEvent_t  g_evj = nullptr;

extern "C" void kernel_launch(void* const* d_in, const int* in_sizes, int n_in,
                              void* d_out, int out_size)
{
    const float* x      = (const float*)d_in[0];
    const int*   batch  = (const int*)d_in[1];
    const float* W_att1 = (const float*)d_in[2];
    const float* b_att1 = (const float*)d_in[3];
    const float* W_att2 = (const float*)d_in[4];
    const float* b_att2 = (const float*)d_in[5];
    const float* Wm     = (const float*)d_in[6];
    const float* bm     = (const float*)d_in[7];
    const float* Wx     = (const float*)d_in[8];
    const float* bx     = (const float*)d_in[9];
    const float* Ww     = (const float*)d_in[10];
    const float* bw     = (const float*)d_in[11];
    const float* Wc1    = (const float*)d_in[12];
    const float* bc1    = (const float*)d_in[13];
    const float* Wc2    = (const float*)d_in[14];
    const float* bc2    = (const float*)d_in[15];
    const float* gamma  = (const float*)d_in[16];
    const float* beta   = (const float*)d_in[17];
    float*       out    = (float*)d_out;

    float *d_s, *d_pooled, *d_bf, *d_W1t;
    __half *d_Wf_h, *d_hid_h, *d_Wc2t_h;
    cudaGetSymbolAddress((void**)&d_s,      g_s);
    cudaGetSymbolAddress((void**)&d_pooled, g_pooled);
    cudaGetSymbolAddress((void**)&d_Wf_h,   g_Wf_h);
    cudaGetSymbolAddress((void**)&d_bf,     g_bf);
    cudaGetSymbolAddress((void**)&d_hid_h,  g_hid_h);
    cudaGetSymbolAddress((void**)&d_Wc2t_h, g_Wc2t_h);
    cudaGetSymbolAddress((void**)&d_W1t,    g_W1t);

    if (g_s2 == nullptr) {
        cudaStreamCreateWithFlags(&g_s2, cudaStreamNonBlocking);
        for (int c = 0; c < NCHUNK; c++)
            cudaEventCreateWithFlags(&g_ev[c], cudaEventDisableTiming);
        cudaEventCreateWithFlags(&g_evj, cudaEventDisableTiming);
    }

    cudaFuncSetAttribute(score_mma_v4,
                         cudaFuncAttributeMaxDynamicSharedMemorySize, V4_SMEM);
    cudaFuncSetAttribute(gemm1_f16,
                         cudaFuncAttributeMaxDynamicSharedMemorySize, G1_SMEM);
    cudaFuncSetAttribute(gemm2_f16_ln,
                         cudaFuncAttributeMaxDynamicSharedMemorySize, G2_SMEM);

    // 1. fused prep
    prep_kernel<<<PREP_BLOCKS, 256>>>(batch, W_att1, Wm, Wx, Ww, Wc1,
                                      bm, bx, bw, bc1, Wc2, d_W1t);

    // 2/3. pipelined score (main) + pool (stream 2), chunked over nodes
    for (int c = 0; c < NCHUNK; c++) {
        score_mma_v4<<<CHUNK_N / 256, 512, V4_SMEM>>>(
            x + (size_t)c * CHUNK_N * 256, d_W1t, b_att1, W_att2, b_att2,
            d_s + (size_t)c * CHUNK_N);
        cudaEventRecord(g_ev[c], 0);
        cudaStreamWaitEvent(g_s2, g_ev[c], 0);
        pool_kernel<<<NUM_GRAPHS, 256, 0, g_s2>>>(x, d_s, d_pooled, c);
    }
    cudaEventRecord(g_evj, g_s2);
    cudaStreamWaitEvent(0, g_evj, 0);

    // 4. hid = gelu(pooled @ Wf + bf)
    gemm1_f16<<<dim3(NUM_GRAPHS / 128, 2), 256, G1_SMEM>>>(d_pooled, d_Wf_h, d_bf, d_hid_h);

    // 5. out = LN(hid @ Wc2 + bc2)
    gemm2_f16_ln<<<NUM_GRAPHS / 128, 256, G2_SMEM>>>(d_hid_h, d_Wc2t_h, bc2, gamma, beta, out);
}

// round 17
// speedup vs baseline: 1.1733x; 1.1733x over previous
#include <cuda_runtime.h>
#include <cuda_fp16.h>
#include <math.h>
#include <stdint.h>

#define N_NODES    524288
#define NUM_GRAPHS 8192
#define HDIM       256

// ---------------- scratch (static device globals; no allocation) ----------------
__device__ float  g_s[N_NODES];
__device__ int    g_start[NUM_GRAPHS + 1];
__device__ float  g_pooled[NUM_GRAPHS * 768];
__device__ __half g_Wf_h[512 * 768];             // fused weights, fp16, N-major
__device__ float  g_bf[512];
__device__ __half g_hid_h[NUM_GRAPHS * 512];     // gelu hidden, fp16
__device__ __half g_Wc2t_h[256 * 512];           // Wc2 transposed fp16 N-major
__device__ float  g_W1t[128 * 256];              // W_att1 transposed (N-major)

// ---------------- helpers ----------------
__device__ __forceinline__ uint32_t f2h2(float a, float b) {
    uint32_t u;
    asm("cvt.rn.f16x2.f32 %0, %2, %1;" : "=r"(u) : "f"(a), "f"(b));
    return u;
}

__device__ __forceinline__ void mma_f16(float c[4],
    uint32_t a0, uint32_t a1, uint32_t a2, uint32_t a3,
    uint32_t b0, uint32_t b1)
{
    asm volatile(
        "mma.sync.aligned.m16n8k16.row.col.f32.f16.f16.f32 "
        "{%0,%1,%2,%3}, {%4,%5,%6,%7}, {%8,%9}, {%0,%1,%2,%3};"
        : "+f"(c[0]), "+f"(c[1]), "+f"(c[2]), "+f"(c[3])
        : "r"(a0), "r"(a1), "r"(a2), "r"(a3), "r"(b0), "r"(b1));
}

// ============================================================================
// fused prep: [0,2048) seg_start | [2048,2080) transpose W1 |
//             [2080,2176) Wf fp16 N-major | [2176,2208) bf |
//             [2208,2336) transpose+cvt Wc2 -> fp16 N-major
// ============================================================================
#define PREP_BLOCKS (2048 + 32 + 96 + 32 + 128)

__global__ __launch_bounds__(256)
void prep_kernel(const int* __restrict__ batch, const float* __restrict__ W1,
                 const float* __restrict__ Wm, const float* __restrict__ Wx,
                 const float* __restrict__ Ww, const float* __restrict__ Wc1,
                 const float* __restrict__ bm, const float* __restrict__ bx,
                 const float* __restrict__ bw, const float* __restrict__ bc1,
                 const float* __restrict__ Wc2, float* __restrict__ W1t)
{
    __shared__ float sbuf[2176];
    const int b = blockIdx.x, tid = threadIdx.x;

    if (b < 2048) {
        int n = b * 256 + tid;
        int v  = batch[n];
        int pv = (n == 0) ? -1 : batch[n - 1];
        if (v >= NUM_GRAPHS) v = NUM_GRAPHS - 1;
        if (pv < -1) pv = -1;
        if (pv > v)  pv = v;
        for (int g = pv + 1; g <= v; g++) g_start[g] = n;
        if (n == N_NODES - 1)
            for (int g = v + 1; g <= NUM_GRAPHS; g++) g_start[g] = N_NODES;
    } else if (b < 2080) {
        float (*t)[33] = (float(*)[33])sbuf;
        int tb = b - 2048;
        int bx0 = (tb & 7) * 32;
        int by0 = (tb >> 3) * 32;
        int tx = tid & 31, ty = tid >> 5;
        #pragma unroll
        for (int i = 0; i < 32; i += 8)
            t[ty + i][tx] = W1[(size_t)(bx0 + ty + i) * 128 + by0 + tx];
        __syncthreads();
        #pragma unroll
        for (int i = 0; i < 32; i += 8)
            W1t[(size_t)(by0 + ty + i) * 256 + bx0 + tx] = t[tx][ty + i];
    } else if (b < 2176) {
        float (*As)[68] = (float(*)[68])sbuf;
        float (*Bs)[68] = (float(*)[68])(sbuf + 16 * 68);
        int wb = b - 2080;
        int bx0 = wb & 3, by0 = (wb >> 2) & 7, z = wb >> 5;
        const float* A = (z == 0) ? Wm : (z == 1) ? Wx : Ww;
        const float* B = Wc1 + (size_t)z * 256 * 512;

        int tx = tid & 15, ty = tid >> 4;
        int ar = tid >> 2, ac = (tid & 3) << 2;
        int br = tid >> 4, bc = (tid & 15) << 2;

        float acc[4][4];
        #pragma unroll
        for (int i = 0; i < 4; i++)
            #pragma unroll
            for (int j = 0; j < 4; j++) acc[i][j] = 0.f;

        for (int k0 = 0; k0 < 256; k0 += 16) {
            float4 va = *(const float4*)(A + (size_t)(bx0 * 64 + ar) * 256 + k0 + ac);
            As[ac + 0][ar] = va.x; As[ac + 1][ar] = va.y;
            As[ac + 2][ar] = va.z; As[ac + 3][ar] = va.w;
            float4 vb = *(const float4*)(B + (size_t)(k0 + br) * 512 + by0 * 64 + bc);
            *(float4*)&Bs[br][bc] = vb;
            __syncthreads();
            #pragma unroll
            for (int kk = 0; kk < 16; kk++) {
                float a[4], bb[4];
                #pragma unroll
                for (int i = 0; i < 4; i++) a[i] = As[kk][ty * 4 + i];
                #pragma unroll
                for (int j = 0; j < 4; j++) bb[j] = Bs[kk][tx * 4 + j];
                #pragma unroll
                for (int i = 0; i < 4; i++)
                    #pragma unroll
                    for (int j = 0; j < 4; j++)
                        acc[i][j] = fmaf(a[i], bb[j], acc[i][j]);
            }
            __syncthreads();
        }
        #pragma unroll
        for (int i = 0; i < 4; i++) {
            int row = z * 256 + bx0 * 64 + ty * 4 + i;
            #pragma unroll
            for (int j = 0; j < 4; j++) {
                int col = by0 * 64 + tx * 4 + j;
                g_Wf_h[(size_t)col * 768 + row] = __float2half(acc[i][j]);
            }
        }
    } else if (b < 2208) {
        int fb = b - 2176;
        int cl = tid & 15, p = tid >> 4;
        int c = fb * 16 + cl;
        float acc = 0.f;
        for (int j = p * 16; j < p * 16 + 16; j++) {
            acc = fmaf(bm[j], Wc1[(size_t)j * 512 + c], acc);
            acc = fmaf(bx[j], Wc1[(size_t)(256 + j) * 512 + c], acc);
            acc = fmaf(bw[j], Wc1[(size_t)(512 + j) * 512 + c], acc);
        }
        sbuf[p * 16 + cl] = acc;
        __syncthreads();
        if (p == 0) {
            float s = bc1[c];
            #pragma unroll
            for (int q = 0; q < 16; q++) s += sbuf[q * 16 + cl];
            g_bf[c] = s;
        }
    } else {
        float (*t)[33] = (float(*)[33])sbuf;
        int tb = b - 2208;
        int kb = (tb & 15) * 32;
        int nb = (tb >> 4) * 32;
        int tx = tid & 31, ty = tid >> 5;
        #pragma unroll
        for (int i = 0; i < 32; i += 8)
            t[ty + i][tx] = Wc2[(size_t)(kb + ty + i) * 256 + nb + tx];
        __syncthreads();
        #pragma unroll
        for (int i = 0; i < 32; i += 8)
            g_Wc2t_h[(size_t)(nb + ty + i) * 512 + kb + tx] = __float2half(t[tx][ty + i]);
    }
}

// ============================================================================
// score v6: s = tanh(x@W1 + b1) @ W2 + b2 via fp16 mma (fp32 accum).
// 256 threads, block tile 128m x 128n, 8 warps (2x4) of 64x32 tiles.
// 2 CTAs per SM (launch_bounds(256,2)) so barriers don't idle the SM.
// ============================================================================
__global__ __launch_bounds__(256, 2)
void score_mma_v6(const float* __restrict__ x, const float* __restrict__ W1t,
                  const float* __restrict__ b1, const float* __restrict__ W2,
                  const float* __restrict__ b2v, float* __restrict__ s_out)
{
    __shared__ __align__(16) uint32_t As2[2][128][20];
    __shared__ __align__(16) uint32_t Bs2[2][128][20];
    __shared__ float psum[128][4];

    const int tid  = threadIdx.x;
    const int lane = tid & 31, warp = tid >> 5;
    const int wy = warp >> 2, wx = warp & 3;   // 2 x 4 warps
    const int g = lane >> 2, t = lane & 3;

    const float* Ab = x + (size_t)blockIdx.x * 128 * 256;

    float c[4][4][4];
    #pragma unroll
    for (int mf = 0; mf < 4; mf++)
        #pragma unroll
        for (int nf = 0; nf < 4; nf++)
            #pragma unroll
            for (int r = 0; r < 4; r++) c[mf][nf][r] = 0.f;

    float4 areg[4], breg[4];

    auto ldg = [&](int ch) {
        #pragma unroll
        for (int i = 0; i < 4; i++) {
            int fid = tid + i * 256;
            int row = fid >> 3, c4 = (fid & 7) << 2;
            areg[i] = *(const float4*)(Ab + (size_t)row * 256 + ch * 32 + c4);
        }
        #pragma unroll
        for (int i = 0; i < 4; i++) {
            int fid = tid + i * 256;
            int row = fid >> 3, c4 = (fid & 7) << 2;
            breg[i] = *(const float4*)(W1t + (size_t)row * 256 + ch * 32 + c4);
        }
    };
    auto sts = [&](int ch) {
        const int buf = ch & 1;
        #pragma unroll
        for (int i = 0; i < 4; i++) {
            int fid = tid + i * 256;
            int row = fid >> 3, h2c = (fid & 7) << 1;
            uint2 v = { f2h2(areg[i].x, areg[i].y), f2h2(areg[i].z, areg[i].w) };
            *(uint2*)&As2[buf][row][h2c] = v;
        }
        #pragma unroll
        for (int i = 0; i < 4; i++) {
            int fid = tid + i * 256;
            int row = fid >> 3, h2c = (fid & 7) << 1;
            uint2 v = { f2h2(breg[i].x, breg[i].y), f2h2(breg[i].z, breg[i].w) };
            *(uint2*)&Bs2[buf][row][h2c] = v;
        }
    };

    ldg(0); sts(0); ldg(1);

    #pragma unroll
    for (int ch = 0; ch < 8; ch++) {
        __syncthreads();
        if (ch + 1 < 8) sts(ch + 1);
        if (ch + 2 < 8) ldg(ch + 2);

        const uint32_t (*A_s)[20] = As2[ch & 1];
        const uint32_t (*B_s)[20] = Bs2[ch & 1];

        #pragma unroll
        for (int kk = 0; kk < 2; kk++) {
            const int k2 = kk * 8;
            uint32_t a[4][4], b[4][2];
            #pragma unroll
            for (int mf = 0; mf < 4; mf++) {
                int row = wy * 64 + mf * 16 + g;
                a[mf][0] = A_s[row][k2 + t];
                a[mf][1] = A_s[row + 8][k2 + t];
                a[mf][2] = A_s[row][k2 + t + 4];
                a[mf][3] = A_s[row + 8][k2 + t + 4];
            }
            #pragma unroll
            for (int nf = 0; nf < 4; nf++) {
                int col = wx * 32 + nf * 8 + g;
                b[nf][0] = B_s[col][k2 + t];
                b[nf][1] = B_s[col][k2 + t + 4];
            }
            #pragma unroll
            for (int mf = 0; mf < 4; mf++)
                #pragma unroll
                for (int nf = 0; nf < 4; nf++)
                    mma_f16(c[mf][nf], a[mf][0], a[mf][1], a[mf][2], a[mf][3],
                            b[nf][0], b[nf][1]);
        }
    }

    // epilogue: tanh(acc + b1) * W2, partial over this warp's 32 cols
    #pragma unroll
    for (int mf = 0; mf < 4; mf++) {
        #pragma unroll
        for (int h = 0; h < 2; h++) {
            float p = 0.f;
            #pragma unroll
            for (int nf = 0; nf < 4; nf++) {
                #pragma unroll
                for (int e = 0; e < 2; e++) {
                    int col = wx * 32 + nf * 8 + 2 * t + e;
                    float v = c[mf][nf][h * 2 + e] + __ldg(&b1[col]);
                    p += tanhf(v) * __ldg(&W2[col]);
                }
            }
            p += __shfl_xor_sync(0xffffffffu, p, 1);
            p += __shfl_xor_sync(0xffffffffu, p, 2);
            if (t == 0) psum[wy * 64 + mf * 16 + g + 8 * h][wx] = p;
        }
    }
    __syncthreads();
    if (tid < 128) {
        float s = psum[tid][0] + psum[tid][1] + psum[tid][2] + psum[tid][3];
        s_out[(size_t)blockIdx.x * 128 + tid] = s + b2v[0];
    }
}

// ---------------- per-graph softmax + pools (combined, single x pass) ---------
__global__ __launch_bounds__(256)
void pool_kernel(const float* __restrict__ x, const float* __restrict__ s,
                 float* __restrict__ pooled)
{
    __shared__ float red[256];
    __shared__ float w_sm[256];
    __shared__ float4 rbuf[256];
    int g = blockIdx.x;
    int beg = g_start[g], end = g_start[g + 1];
    if (beg < 0) beg = 0;
    if (end > N_NODES) end = N_NODES;
    int cnt = end - beg;
    int tid = threadIdx.x;

    float m = -3.402823466e38f;
    for (int i = beg + tid; i < end; i += 256) m = fmaxf(m, s[i]);
    red[tid] = m; __syncthreads();
    for (int off = 128; off > 0; off >>= 1) {
        if (tid < off) red[tid] = fmaxf(red[tid], red[tid + off]);
        __syncthreads();
    }
    float smax = red[0];
    __syncthreads();

    float e = 0.f;
    for (int i = beg + tid; i < end; i += 256) e += expf(s[i] - smax);
    red[tid] = e; __syncthreads();
    for (int off = 128; off > 0; off >>= 1) {
        if (tid < off) red[tid] += red[tid + off];
        __syncthreads();
    }
    float inv_den = (cnt > 0) ? (1.f / red[0]) : 0.f;
    __syncthreads();

    const int nl = tid >> 6;
    const int c4 = (tid & 63) << 2;
    float4 aw = {0.f, 0.f, 0.f, 0.f}, as4 = {0.f, 0.f, 0.f, 0.f};
    float4 am = {-3.402823466e38f, -3.402823466e38f, -3.402823466e38f, -3.402823466e38f};

    for (int c0 = beg; c0 < end; c0 += 256) {
        int clen = min(256, end - c0);
        if (tid < clen) w_sm[tid] = expf(s[c0 + tid] - smax) * inv_den;
        __syncthreads();
        const float* xb = x + (size_t)c0 * 256 + c4;
        int j = nl;
        for (; j + 12 < clen; j += 16) {
            float w0 = w_sm[j],     w1 = w_sm[j + 4];
            float w2 = w_sm[j + 8], w3 = w_sm[j + 12];
            float4 x0 = *(const float4*)(xb + (size_t)j * 256);
            float4 x1 = *(const float4*)(xb + (size_t)(j + 4) * 256);
            float4 x2 = *(const float4*)(xb + (size_t)(j + 8) * 256);
            float4 x3 = *(const float4*)(xb + (size_t)(j + 12) * 256);
            aw.x = fmaf(w0, x0.x, aw.x); aw.y = fmaf(w0, x0.y, aw.y);
            aw.z = fmaf(w0, x0.z, aw.z); aw.w = fmaf(w0, x0.w, aw.w);
            as4.x += x0.x; as4.y += x0.y; as4.z += x0.z; as4.w += x0.w;
            am.x = fmaxf(am.x, x0.x); am.y = fmaxf(am.y, x0.y);
            am.z = fmaxf(am.z, x0.z); am.w = fmaxf(am.w, x0.w);
            aw.x = fmaf(w1, x1.x, aw.x); aw.y = fmaf(w1, x1.y, aw.y);
            aw.z = fmaf(w1, x1.z, aw.z); aw.w = fmaf(w1, x1.w, aw.w);
            as4.x += x1.x; as4.y += x1.y; as4.z += x1.z; as4.w += x1.w;
            am.x = fmaxf(am.x, x1.x); am.y = fmaxf(am.y, x1.y);
            am.z = fmaxf(am.z, x1.z); am.w = fmaxf(am.w, x1.w);
            aw.x = fmaf(w2, x2.x, aw.x); aw.y = fmaf(w2, x2.y, aw.y);
            aw.z = fmaf(w2, x2.z, aw.z); aw.w = fmaf(w2, x2.w, aw.w);
            as4.x += x2.x; as4.y += x2.y; as4.z += x2.z; as4.w += x2.w;
            am.x = fmaxf(am.x, x2.x); am.y = fmaxf(am.y, x2.y);
            am.z = fmaxf(am.z, x2.z); am.w = fmaxf(am.w, x2.w);
            aw.x = fmaf(w3, x3.x, aw.x); aw.y = fmaf(w3, x3.y, aw.y);
            aw.z = fmaf(w3, x3.z, aw.z); aw.w = fmaf(w3, x3.w, aw.w);
            as4.x += x3.x; as4.y += x3.y; as4.z += x3.z; as4.w += x3.w;
            am.x = fmaxf(am.x, x3.x); am.y = fmaxf(am.y, x3.y);
            am.z = fmaxf(am.z, x3.z); am.w = fmaxf(am.w, x3.w);
        }
        for (; j < clen; j += 4) {
            float w = w_sm[j];
            float4 xv = *(const float4*)(xb + (size_t)j * 256);
            aw.x = fmaf(w, xv.x, aw.x); aw.y = fmaf(w, xv.y, aw.y);
            aw.z = fmaf(w, xv.z, aw.z); aw.w = fmaf(w, xv.w, aw.w);
            as4.x += xv.x; as4.y += xv.y; as4.z += xv.z; as4.w += xv.w;
            am.x = fmaxf(am.x, xv.x); am.y = fmaxf(am.y, xv.y);
            am.z = fmaxf(am.z, xv.z); am.w = fmaxf(am.w, xv.w);
        }
        __syncthreads();
    }

    size_t base = (size_t)g * 768;
    float inv_c = (cnt > 0) ? (1.f / (float)cnt) : 0.f;

    rbuf[tid] = as4; __syncthreads();
    if (tid < 64) {
        float4 a = rbuf[tid], b = rbuf[tid + 64], c = rbuf[tid + 128], d = rbuf[tid + 192];
        float4 r = { (a.x + b.x + c.x + d.x) * inv_c, (a.y + b.y + c.y + d.y) * inv_c,
                     (a.z + b.z + c.z + d.z) * inv_c, (a.w + b.w + c.w + d.w) * inv_c };
        *(float4*)(pooled + base + tid * 4) = r;
    }
    __syncthreads();
    rbuf[tid] = am; __syncthreads();
    if (tid < 64) {
        float4 a = rbuf[tid], b = rbuf[tid + 64], c = rbuf[tid + 128], d = rbuf[tid + 192];
        float4 r = { fmaxf(fmaxf(a.x, b.x), fmaxf(c.x, d.x)),
                     fmaxf(fmaxf(a.y, b.y), fmaxf(c.y, d.y)),
                     fmaxf(fmaxf(a.z, b.z), fmaxf(c.z, d.z)),
                     fmaxf(fmaxf(a.w, b.w), fmaxf(c.w, d.w)) };
        if (cnt <= 0) r = make_float4(0.f, 0.f, 0.f, 0.f);
        *(float4*)(pooled + base + 256 + tid * 4) = r;
    }
    __syncthreads();
    rbuf[tid] = aw; __syncthreads();
    if (tid < 64) {
        float4 a = rbuf[tid], b = rbuf[tid + 64], c = rbuf[tid + 128], d = rbuf[tid + 192];
        float4 r = { a.x + b.x + c.x + d.x, a.y + b.y + c.y + d.y,
                     a.z + b.z + c.z + d.z, a.w + b.w + c.w + d.w };
        if (cnt <= 0) r = make_float4(0.f, 0.f, 0.f, 0.f);
        *(float4*)(pooled + base + 512 + tid * 4) = r;
    }
}

// ============================================================================
// gemm1 fp16 (wide warp tiles): hid = gelu(pooled @ Wf + bf) -> fp16
// ============================================================================
#define G1_AW (2 * 128 * 20)
#define G1_BW (2 * 256 * 20)
#define G1_SMEM ((G1_AW + G1_BW) * 4)

__global__ __launch_bounds__(256)
void gemm1_f16(const float* __restrict__ A, const __half* __restrict__ Bh,
               const float* __restrict__ bias, __half* __restrict__ C)
{
    extern __shared__ uint32_t sm[];
    uint32_t* As2 = sm;
    uint32_t* Bs2 = sm + G1_AW;

    const int tid  = threadIdx.x;
    const int lane = tid & 31, warp = tid >> 5;
    const int wy = warp >> 2, wx = warp & 3;
    const int g = lane >> 2, t = lane & 3;

    const float*  Ab = A  + (size_t)blockIdx.x * 128 * 768;
    const __half* Bb = Bh + (size_t)blockIdx.y * 256 * 768;

    float c[4][8][4];
    #pragma unroll
    for (int mf = 0; mf < 4; mf++)
        #pragma unroll
        for (int nf = 0; nf < 8; nf++)
            #pragma unroll
            for (int r = 0; r < 4; r++) c[mf][nf][r] = 0.f;

    float4 areg[4];
    uint4  breg[4];

    auto ldg = [&](int ch) {
        #pragma unroll
        for (int i = 0; i < 4; i++) {
            int fid = tid + i * 256;
            int row = fid >> 3, c4 = (fid & 7) << 2;
            areg[i] = *(const float4*)(Ab + (size_t)row * 768 + ch * 32 + c4);
        }
        #pragma unroll
        for (int i = 0; i < 4; i++) {
            int fid = tid + i * 256;
            int col = fid >> 2, q = fid & 3;
            breg[i] = *(const uint4*)(Bb + (size_t)col * 768 + ch * 32 + q * 8);
        }
    };
    auto sts = [&](int ch) {
        const int buf = ch & 1;
        #pragma unroll
        for (int i = 0; i < 4; i++) {
            int fid = tid + i * 256;
            int row = fid >> 3, h2c = (fid & 7) << 1;
            uint2 v = { f2h2(areg[i].x, areg[i].y), f2h2(areg[i].z, areg[i].w) };
            *(uint2*)&As2[(buf * 128 + row) * 20 + h2c] = v;
        }
        #pragma unroll
        for (int i = 0; i < 4; i++) {
            int fid = tid + i * 256;
            int col = fid >> 2, q = fid & 3;
            *(uint4*)&Bs2[(buf * 256 + col) * 20 + q * 4] = breg[i];
        }
    };

    ldg(0); sts(0); ldg(1);

    for (int ch = 0; ch < 24; ch++) {
        __syncthreads();
        if (ch + 1 < 24) sts(ch + 1);
        if (ch + 2 < 24) ldg(ch + 2);

        const uint32_t* A_s = As2 + (ch & 1) * 128 * 20;
        const uint32_t* B_s = Bs2 + (ch & 1) * 256 * 20;

        #pragma unroll
        for (int kk = 0; kk < 2; kk++) {
            const int k2 = kk * 8;
            uint32_t a[4][4], b[8][2];
            #pragma unroll
            for (int mf = 0; mf < 4; mf++) {
                int row = wy * 64 + mf * 16 + g;
                a[mf][0] = A_s[row * 20 + k2 + t];
                a[mf][1] = A_s[(row + 8) * 20 + k2 + t];
                a[mf][2] = A_s[row * 20 + k2 + t + 4];
                a[mf][3] = A_s[(row + 8) * 20 + k2 + t + 4];
            }
            #pragma unroll
            for (int nf = 0; nf < 8; nf++) {
                int col = wx * 64 + nf * 8 + g;
                b[nf][0] = B_s[col * 20 + k2 + t];
                b[nf][1] = B_s[col * 20 + k2 + t + 4];
            }
            #pragma unroll
            for (int mf = 0; mf < 4; mf++)
                #pragma unroll
                for (int nf = 0; nf < 8; nf++)
                    mma_f16(c[mf][nf], a[mf][0], a[mf][1], a[mf][2], a[mf][3],
                            b[nf][0], b[nf][1]);
        }
    }

    #pragma unroll
    for (int mf = 0; mf < 4; mf++) {
        #pragma unroll
        for (int h = 0; h < 2; h++) {
            int row = blockIdx.x * 128 + wy * 64 + mf * 16 + g + 8 * h;
            #pragma unroll
            for (int nf = 0; nf < 8; nf++) {
                int col = blockIdx.y * 256 + wx * 64 + nf * 8 + 2 * t;
                float v0 = c[mf][nf][h * 2 + 0] + __ldg(&bias[col]);
                float v1 = c[mf][nf][h * 2 + 1] + __ldg(&bias[col + 1]);
                v0 = 0.5f * v0 * (1.f + erff(v0 * 0.70710678118654752f));
                v1 = 0.5f * v1 * (1.f + erff(v1 * 0.70710678118654752f));
                *(uint32_t*)&C[(size_t)row * 512 + col] = f2h2(v0, v1);
            }
        }
    }
}

// ============================================================================
// gemm2+LN fused: out = LN(hid_h[8192,512] @ Wc2t_h + bc2) * gamma + beta
// ============================================================================
#define G2_AW (2 * 128 * 20)
#define G2_BW (2 * 256 * 20)
#define G2_SMEM ((G2_AW + G2_BW + 128 * 4 * 2) * 4)

__global__ __launch_bounds__(256)
void gemm2_f16_ln(const __half* __restrict__ A, const __half* __restrict__ Bh,
                  const float* __restrict__ bias, const float* __restrict__ gamma,
                  const float* __restrict__ beta, float* __restrict__ out)
{
    extern __shared__ uint32_t sm[];
    uint32_t* As2  = sm;
    uint32_t* Bs2  = sm + G2_AW;
    float*   psumS = (float*)(sm + G2_AW + G2_BW);
    float*   psumQ = psumS + 128 * 4;

    const int tid  = threadIdx.x;
    const int lane = tid & 31, warp = tid >> 5;
    const int wy = warp >> 2, wx = warp & 3;
    const int g = lane >> 2, t = lane & 3;

    const __half* Ab = A + (size_t)blockIdx.x * 128 * 512;

    float c[4][8][4];
    #pragma unroll
    for (int mf = 0; mf < 4; mf++)
        #pragma unroll
        for (int nf = 0; nf < 8; nf++)
            #pragma unroll
            for (int r = 0; r < 4; r++) c[mf][nf][r] = 0.f;

    uint4 areg[2], breg[4];

    auto ldg = [&](int ch) {
        #pragma unroll
        for (int i = 0; i < 2; i++) {
            int fid = tid + i * 256;
            int row = fid >> 2, q = fid & 3;
            areg[i] = *(const uint4*)(Ab + (size_t)row * 512 + ch * 32 + q * 8);
        }
        #pragma unroll
        for (int i = 0; i < 4; i++) {
            int fid = tid + i * 256;
            int col = fid >> 2, q = fid & 3;
            breg[i] = *(const uint4*)(Bh + (size_t)col * 512 + ch * 32 + q * 8);
        }
    };
    auto sts = [&](int ch) {
        const int buf = ch & 1;
        #pragma unroll
        for (int i = 0; i < 2; i++) {
            int fid = tid + i * 256;
            int row = fid >> 2, q = fid & 3;
            *(uint4*)&As2[(buf * 128 + row) * 20 + q * 4] = areg[i];
        }
        #pragma unroll
        for (int i = 0; i < 4; i++) {
            int fid = tid + i * 256;
            int col = fid >> 2, q = fid & 3;
            *(uint4*)&Bs2[(buf * 256 + col) * 20 + q * 4] = breg[i];
        }
    };

    ldg(0); sts(0); ldg(1);

    for (int ch = 0; ch < 16; ch++) {
        __syncthreads();
        if (ch + 1 < 16) sts(ch + 1);
        if (ch + 2 < 16) ldg(ch + 2);

        const uint32_t* A_s = As2 + (ch & 1) * 128 * 20;
        const uint32_t* B_s = Bs2 + (ch & 1) * 256 * 20;

        #pragma unroll
        for (int kk = 0; kk < 2; kk++) {
            const int k2 = kk * 8;
            uint32_t a[4][4], b[8][2];
            #pragma unroll
            for (int mf = 0; mf < 4; mf++) {
                int row = wy * 64 + mf * 16 + g;
                a[mf][0] = A_s[row * 20 + k2 + t];
                a[mf][1] = A_s[(row + 8) * 20 + k2 + t];
                a[mf][2] = A_s[row * 20 + k2 + t + 4];
                a[mf][3] = A_s[(row + 8) * 20 + k2 + t + 4];
            }
            #pragma unroll
            for (int nf = 0; nf < 8; nf++) {
                int col = wx * 64 + nf * 8 + g;
                b[nf][0] = B_s[col * 20 + k2 + t];
                b[nf][1] = B_s[col * 20 + k2 + t + 4];
            }
            #pragma unroll
            for (int mf = 0; mf < 4; mf++)
                #pragma unroll
                for (int nf = 0; nf < 8; nf++)
                    mma_f16(c[mf][nf], a[mf][0], a[mf][1], a[mf][2], a[mf][3],
                            b[nf][0], b[nf][1]);
        }
    }
    __syncthreads();

    #pragma unroll
    for (int mf = 0; mf < 4; mf++) {
        #pragma unroll
        for (int h = 0; h < 2; h++) {
            float ps = 0.f, pq = 0.f;
            #pragma unroll
            for (int nf = 0; nf < 8; nf++) {
                #pragma unroll
                for (int e = 0; e < 2; e++) {
                    int col = wx * 64 + nf * 8 + 2 * t + e;
                    float v = c[mf][nf][h * 2 + e] + __ldg(&bias[col]);
                    c[mf][nf][h * 2 + e] = v;
                    ps += v; pq += v * v;
                }
            }
            ps += __shfl_xor_sync(0xffffffffu, ps, 1);
            ps += __shfl_xor_sync(0xffffffffu, ps, 2);
            pq += __shfl_xor_sync(0xffffffffu, pq, 1);
            pq += __shfl_xor_sync(0xffffffffu, pq, 2);
            if (t == 0) {
                int r = wy * 64 + mf * 16 + g + 8 * h;
                psumS[r * 4 + wx] = ps;
                psumQ[r * 4 + wx] = pq;
            }
        }
    }
    __syncthreads();

    #pragma unroll
    for (int mf = 0; mf < 4; mf++) {
        #pragma unroll
        for (int h = 0; h < 2; h++) {
            int r = wy * 64 + mf * 16 + g + 8 * h;
            float sum = psumS[r * 4] + psumS[r * 4 + 1] + psumS[r * 4 + 2] + psumS[r * 4 + 3];
            float sq  = psumQ[r * 4] + psumQ[r * 4 + 1] + psumQ[r * 4 + 2] + psumQ[r * 4 + 3];
            float mu  = sum * (1.f / 256.f);
            float var = sq * (1.f / 256.f) - mu * mu;
            float rs  = rsqrtf(var + 1e-5f);
            int grow = blockIdx.x * 128 + r;
            #pragma unroll
            for (int nf = 0; nf < 8; nf++) {
                int col = wx * 64 + nf * 8 + 2 * t;
                float v0 = (c[mf][nf][h * 2 + 0] - mu) * rs * __ldg(&gamma[col])     + __ldg(&beta[col]);
                float v1 = (c[mf][nf][h * 2 + 1] - mu) * rs * __ldg(&gamma[col + 1]) + __ldg(&beta[col + 1]);
                float2 st = { v0, v1 };
                *(float2*)(out + (size_t)grow * 256 + col) = st;
            }
        }
    }
}

// ---------------- launcher ----------------
extern "C" void kernel_launch(void* const* d_in, const int* in_sizes, int n_in,
                              void* d_out, int out_size)
{
    const float* x      = (const float*)d_in[0];
    const int*   batch  = (const int*)d_in[1];
    const float* W_att1 = (const float*)d_in[2];
    const float* b_att1 = (const float*)d_in[3];
    const float* W_att2 = (const float*)d_in[4];
    const float* b_att2 = (const float*)d_in[5];
    const float* Wm     = (const float*)d_in[6];
    const float* bm     = (const float*)d_in[7];
    const float* Wx     = (const float*)d_in[8];
    const float* bx     = (const float*)d_in[9];
    const float* Ww     = (const float*)d_in[10];
    const float* bw     = (const float*)d_in[11];
    const float* Wc1    = (const float*)d_in[12];
    const float* bc1    = (const float*)d_in[13];
    const float* Wc2    = (const float*)d_in[14];
    const float* bc2    = (const float*)d_in[15];
    const float* gamma  = (const float*)d_in[16];
    const float* beta   = (const float*)d_in[17];
    float*       out    = (float*)d_out;

    float *d_s, *d_pooled, *d_bf, *d_W1t;
    __half *d_Wf_h, *d_hid_h, *d_Wc2t_h;
    cudaGetSymbolAddress((void**)&d_s,      g_s);
    cudaGetSymbolAddress((void**)&d_pooled, g_pooled);
    cudaGetSymbolAddress((void**)&d_Wf_h,   g_Wf_h);
    cudaGetSymbolAddress((void**)&d_bf,     g_bf);
    cudaGetSymbolAddress((void**)&d_hid_h,  g_hid_h);
    cudaGetSymbolAddress((void**)&d_Wc2t_h, g_Wc2t_h);
    cudaGetSymbolAddress((void**)&d_W1t,    g_W1t);

    cudaFuncSetAttribute(gemm1_f16,
                         cudaFuncAttributeMaxDynamicSharedMemorySize, G1_SMEM);
    cudaFuncSetAttribute(gemm2_f16_ln,
                         cudaFuncAttributeMaxDynamicSharedMemorySize, G2_SMEM);

    // 1. fused prep
    prep_kernel<<<PREP_BLOCKS, 256>>>(batch, W_att1, Wm, Wx, Ww, Wc1,
                                      bm, bx, bw, bc1, Wc2, d_W1t);

    // 2. node attention scores (fp16 mma, 2 CTAs/SM)
    score_mma_v6<<<N_NODES / 128, 256>>>(x, d_W1t, b_att1, W_att2, b_att2, d_s);

    // 3. per-graph softmax + pools (combined, one x pass)
    pool_kernel<<<NUM_GRAPHS, 256>>>(x, d_s, d_pooled);

    // 4. hid = gelu(pooled @ Wf + bf)
    gemm1_f16<<<dim3(NUM_GRAPHS / 128, 2), 256, G1_SMEM>>>(d_pooled, d_Wf_h, d_bf, d_hid_h);

    // 5. out = LN(hid @ Wc2 + bc2)
    gemm2_f16_ln<<<NUM_GRAPHS / 128, 256, G2_SMEM>>>(d_hid_h, d_Wc2t_h, bc2, gamma, beta, out);
}